// round 5
// baseline (speedup 1.0000x reference)
#include <cuda_runtime.h>
#include <cuda_fp16.h>
#include <cstdint>

#define HH 256
#define WW 256
#define C 64
#define O 64
#define B 16
#define NK 4
#define GROUPS 8

#define XSP2 328                 // half2 plane stride: 18*18=324 pad->328 (==8 mod 32)
#define NPLANE2 32               // 64 channels / 2 per half2
#define A_TAP_HALVES 4096        // 2 wo * 4 kt * 2 mt * 32 lanes * 8 halves
#define A_TAP_BYTES  8192

// ---- scratch ----
__device__ __half g_wt[B * 9 * O * C];   // fp16 weights, MMA-fragment-ordered
__device__ float g_sum[B * GROUPS];
__device__ float g_sumsq[B * GROUPS];

__device__ __forceinline__ void mma_f16(float* d, const uint32_t* a,
                                        uint32_t b0, uint32_t b1) {
    asm("mma.sync.aligned.m16n8k16.row.col.f32.f16.f16.f32 "
        "{%0,%1,%2,%3}, {%4,%5,%6,%7}, {%8,%9}, {%0,%1,%2,%3};"
        : "+f"(d[0]), "+f"(d[1]), "+f"(d[2]), "+f"(d[3])
        : "r"(a[0]), "r"(a[1]), "r"(a[2]), "r"(a[3]), "r"(b0), "r"(b1));
}

__device__ __forceinline__ void cp_async16(uint32_t dst_smem, const void* src) {
    asm volatile("cp.async.cg.shared.global [%0], [%1], 16;"
                 :: "r"(dst_smem), "l"(src));
}

// ============================================================================
// Kernel 0: softmax mix + modulate + demodulate -> fp16 fragment-ordered g_wt.
// Fragment layout (halves): [b][tap][wo(2)][kt(4)][mt(2)][lane(32)][pos(8)]
//   for mma.m16n8k16 A (row-major 16x16):
//   o = wo*32+mt*16+row, c = kt*16+kk; rA = (kk>=8)*2 + (row>=8);
//   lane = (row&7)*4 + ((kk&7)>>1); pos = rA*2 + (kk&1)
// ============================================================================
__global__ void weight_kernel(const float* __restrict__ mod,
                              const float* __restrict__ kmod,
                              const float* __restrict__ cw) {
    int o = blockIdx.x;
    int b = blockIdx.y;
    int i = threadIdx.x;  // input channel 0..63

    float k0 = kmod[b * NK + 0], k1 = kmod[b * NK + 1];
    float k2 = kmod[b * NK + 2], k3 = kmod[b * NK + 3];
    float m = fmaxf(fmaxf(k0, k1), fmaxf(k2, k3));
    float e0 = __expf(k0 - m), e1 = __expf(k1 - m);
    float e2 = __expf(k2 - m), e3 = __expf(k3 - m);
    float inv = 1.0f / (e0 + e1 + e2 + e3);
    float a0 = e0 * inv, a1 = e1 * inv, a2 = e2 * inv, a3 = e3 * inv;

    float mi = mod[b * C + i] + 1.0f;

    float wv[9];
    float ss = 0.0f;
#pragma unroll
    for (int k = 0; k < 9; k++) {
        int base = (o * C + i) * 9 + k;
        const int stride = O * C * 9;
        float v = a0 * cw[base] + a1 * cw[stride + base] +
                  a2 * cw[2 * stride + base] + a3 * cw[3 * stride + base];
        v *= mi;
        wv[k] = v;
        ss += v * v;
    }
#pragma unroll
    for (int off = 16; off; off >>= 1)
        ss += __shfl_xor_sync(0xffffffffu, ss, off);
    __shared__ float sh[2];
    if ((i & 31) == 0) sh[i >> 5] = ss;
    __syncthreads();
    float tot = sh[0] + sh[1];
    float innorm = rsqrtf(fmaxf(tot, 1e-8f));

    // fragment coordinates for (o, c=i)
    int wo = o >> 5;
    int m5 = o & 31;
    int mt = m5 >> 4;
    int row = m5 & 15;
    int kt = i >> 4;
    int kk = i & 15;
    int rA = ((kk >= 8) ? 2 : 0) + ((row >= 8) ? 1 : 0);
    int lane = ((row & 7) << 2) | ((kk & 7) >> 1);
    int pos = rA * 2 + (kk & 1);

#pragma unroll
    for (int k = 0; k < 9; k++) {
        long long idx = (((((long long)(b * 9 + k) * 2 + wo) * 4 + kt) * 2 + mt)
                         * 32 + lane) * 8 + pos;
        g_wt[idx] = __float2half_rn(wv[k] * innorm);
    }

    if (o == 0 && i < GROUPS) {
        g_sum[b * GROUPS + i] = 0.0f;
        g_sumsq[b * GROUPS + i] = 0.0f;
    }
}

// ============================================================================
// Kernel 1: fp16 tensor-core conv (9 shifted GEMMs, m16n8k16) + GN stats.
// grid (16,16,B), 256 threads = 8 warps, 2 CTAs/SM.
// smem: xs2 [32 half2-planes][XSP2] channel-pair-packed halo tile (41984 B)
//       + 2 x fragment-ordered A tap buffers (16384 B)
// ============================================================================
__global__ void __launch_bounds__(256, 2)
conv_kernel(const float* __restrict__ x, float* __restrict__ y) {
    extern __shared__ char smem[];
    __half2* xs2 = (__half2*)smem;                                // 32*XSP2
    __half* as_h = (__half*)(smem + NPLANE2 * XSP2 * 4);          // 2*A_TAP_HALVES
    __shared__ float gsum[GROUPS], gsq[GROUPS];

    int b = blockIdx.z;
    int h0 = blockIdx.y * 16;
    int w0 = blockIdx.x * 16;
    int tid = threadIdx.x;
    int wid = tid >> 5, lane = tid & 31;
    int wo = wid & 1;        // O half
    int wn = wid >> 1;       // pixel quarter: tile rows 4*wn..4*wn+3
    int g2 = lane >> 2;      // 0..7
    int qp = lane & 3;       // 0..3

    if (tid < GROUPS) { gsum[tid] = 0.0f; gsq[tid] = 0.0f; }

    const __half* wtb = g_wt + (long long)b * 9 * O * C;
    uint32_t as_smem = (uint32_t)__cvta_generic_to_shared(as_h);

    // prologue: A tap0 -> buf0 (8192 B = 512 x 16B, 2 chunks/thread)
#pragma unroll
    for (int j = 0; j < 2; j++) {
        int chunk = tid + j * 256;
        cp_async16(as_smem + chunk * 16, wtb + chunk * 8);
    }
    asm volatile("cp.async.commit_group;");

    // ---- stage x halo tile as channel-pair half2 (zero padded) ----
    const float* xb = x + (long long)b * C * HH * WW;
    for (int idx = tid; idx < NPLANE2 * 324; idx += 256) {
        int ci2 = idx / 324;
        int rem = idx - ci2 * 324;
        int rr = rem / 18;
        int cc = rem - rr * 18;
        int gh = h0 + rr - 1;
        int gw = w0 + cc - 1;
        float v0 = 0.0f, v1 = 0.0f;
        if ((unsigned)gh < HH && (unsigned)gw < WW) {
            const float* p = xb + (2 * ci2) * (HH * WW) + gh * WW + gw;
            v0 = p[0];
            v1 = p[HH * WW];
        }
        xs2[ci2 * XSP2 + rr * 18 + cc] = __floats2half2_rn(v0, v1);
    }
    asm volatile("cp.async.wait_group 0;");
    __syncthreads();

    float acc[2][8][4];
#pragma unroll
    for (int mt = 0; mt < 2; mt++)
#pragma unroll
        for (int nt = 0; nt < 8; nt++)
#pragma unroll
            for (int r = 0; r < 4; r++) acc[mt][nt][r] = 0.0f;

#pragma unroll 1
    for (int tap = 0; tap < 9; tap++) {
        int buf = tap & 1;
        if (tap < 8) {
            const __half* src = wtb + (tap + 1) * (O * C);
            uint32_t dst = as_smem + (buf ^ 1) * A_TAP_BYTES;
#pragma unroll
            for (int j = 0; j < 2; j++) {
                int chunk = tid + j * 256;
                cp_async16(dst + chunk * 16, src + chunk * 8);
            }
            asm volatile("cp.async.commit_group;");
        }

        int kh = tap / 3;
        int kw = tap - kh * 3;
        // A fragments: base for this warp's wo
        const uint4* a_base = (const uint4*)(as_h + buf * A_TAP_HALVES) +
                              (wo * 4) * 2 * 32 + lane;   // + (kt*2+mt)*32
        const __half2* b_base = xs2 + qp * XSP2 + (wn * 4 + kh) * 18 + kw + g2;

#pragma unroll
        for (int kt = 0; kt < 4; kt++) {
            uint4 af0 = a_base[(kt * 2 + 0) * 32];
            uint4 af1 = a_base[(kt * 2 + 1) * 32];
            const __half2* bp = b_base + kt * 8 * XSP2;
#pragma unroll
            for (int nt = 0; nt < 8; nt++) {
                int po = (nt >> 1) * 18 + (nt & 1) * 8;
                uint32_t b0 = *(const uint32_t*)(bp + po);
                uint32_t b1 = *(const uint32_t*)(bp + 4 * XSP2 + po);
                mma_f16(acc[0][nt], (const uint32_t*)&af0, b0, b1);
                mma_f16(acc[1][nt], (const uint32_t*)&af1, b0, b1);
            }
        }

        if (tap < 8) asm volatile("cp.async.wait_group 0;");
        __syncthreads();
    }

    // ---- store conv output (fp32) + GN partial stats ----
    float* yb = y + (long long)b * O * HH * WW;
    float s[2][2] = {{0, 0}, {0, 0}}, s2[2][2] = {{0, 0}, {0, 0}};
#pragma unroll
    for (int mt = 0; mt < 2; mt++) {
#pragma unroll
        for (int nt = 0; nt < 8; nt++) {
            int gh = h0 + wn * 4 + (nt >> 1);
            int gw = w0 + (nt & 1) * 8 + 2 * qp;
            int o_lo = wo * 32 + mt * 16 + g2;
            float c0 = acc[mt][nt][0], c1 = acc[mt][nt][1];
            float c2 = acc[mt][nt][2], c3 = acc[mt][nt][3];
            *(float2*)(yb + o_lo * (HH * WW) + gh * WW + gw) = make_float2(c0, c1);
            *(float2*)(yb + (o_lo + 8) * (HH * WW) + gh * WW + gw) = make_float2(c2, c3);
            s[mt][0] += c0 + c1;  s2[mt][0] += c0 * c0 + c1 * c1;
            s[mt][1] += c2 + c3;  s2[mt][1] += c2 * c2 + c3 * c3;
        }
    }
#pragma unroll
    for (int off = 16; off; off >>= 1) {
#pragma unroll
        for (int mt = 0; mt < 2; mt++)
#pragma unroll
            for (int hi = 0; hi < 2; hi++) {
                s[mt][hi]  += __shfl_xor_sync(0xffffffffu, s[mt][hi], off);
                s2[mt][hi] += __shfl_xor_sync(0xffffffffu, s2[mt][hi], off);
            }
    }
    if (lane == 0) {
#pragma unroll
        for (int mt = 0; mt < 2; mt++)
#pragma unroll
            for (int hi = 0; hi < 2; hi++) {
                int g = wo * 4 + mt * 2 + hi;
                atomicAdd(&gsum[g], s[mt][hi]);
                atomicAdd(&gsq[g], s2[mt][hi]);
            }
    }
    __syncthreads();
    if (tid < GROUPS) {
        atomicAdd(&g_sum[b * GROUPS + tid], gsum[tid]);
        atomicAdd(&g_sumsq[b * GROUPS + tid], gsq[tid]);
    }
}

// ============================================================================
// Kernel 2: GroupNorm finalize + SiLU, in-place, float4 vectorized.
// ============================================================================
__global__ void norm_kernel(float* __restrict__ y,
                            const float* __restrict__ gamma,
                            const float* __restrict__ beta) {
    long long i = (long long)blockIdx.x * blockDim.x + threadIdx.x;
    long long base = i * 4;
    int cidx = (int)(base >> 16);
    int b = cidx >> 6;
    int c = cidx & 63;
    int g = c >> 3;

    const float invN = 1.0f / (8.0f * HH * WW);
    float mean = g_sum[b * GROUPS + g] * invN;
    float var = g_sumsq[b * GROUPS + g] * invN - mean * mean;
    float istd = rsqrtf(var + 1e-5f);
    float ga = gamma[c], be = beta[c];

    float4 v = *(float4*)&y[base];
    float* vp = &v.x;
#pragma unroll
    for (int k = 0; k < 4; k++) {
        float t = (vp[k] - mean) * istd * ga + be;
        vp[k] = t / (1.0f + __expf(-t));
    }
    *(float4*)&y[base] = v;
}

// ============================================================================
extern "C" void kernel_launch(void* const* d_in, const int* in_sizes, int n_in,
                              void* d_out, int out_size) {
    const float* x     = (const float*)d_in[0];
    const float* mod   = (const float*)d_in[1];
    const float* kmod  = (const float*)d_in[2];
    const float* cw    = (const float*)d_in[3];
    const float* gamma = (const float*)d_in[4];
    const float* beta  = (const float*)d_in[5];
    float* out = (float*)d_out;

    const int smem = NPLANE2 * XSP2 * 4 + 2 * A_TAP_BYTES;  // 41984+16384 = 58368
    cudaFuncSetAttribute(conv_kernel,
                         cudaFuncAttributeMaxDynamicSharedMemorySize, smem);

    weight_kernel<<<dim3(O, B), 64>>>(mod, kmod, cw);
    conv_kernel<<<dim3(16, 16, B), 256, smem>>>(x, out);
    norm_kernel<<<(B * O * HH * WW / 4) / 256, 256>>>(out, gamma, beta);
}

// round 6
// speedup vs baseline: 1.0007x; 1.0007x over previous
#include <cuda_runtime.h>
#include <cuda_fp16.h>
#include <cstdint>

#define HH 256
#define WW 256
#define C 64
#define O 64
#define B 16
#define NK 4
#define GROUPS 8

#define XSP2 328                 // half2 plane stride: 18*18=324 pad->328 (==8 mod 32)
#define NPLANE2 32               // 64 channels / 2 per half2
#define A_TAP_HALVES 4096        // 2 wo * 4 kt * 2 mt * 32 lanes * 8 halves
#define A_TAP_BYTES  8192

// ---- scratch ----
__device__ __half g_wt[B * 9 * O * C];   // fp16 weights, MMA-fragment-ordered
__device__ float g_sum[B * GROUPS];
__device__ float g_sumsq[B * GROUPS];

__device__ __forceinline__ void mma_f16(float* d, const uint32_t* a,
                                        uint32_t b0, uint32_t b1) {
    asm("mma.sync.aligned.m16n8k16.row.col.f32.f16.f16.f32 "
        "{%0,%1,%2,%3}, {%4,%5,%6,%7}, {%8,%9}, {%0,%1,%2,%3};"
        : "+f"(d[0]), "+f"(d[1]), "+f"(d[2]), "+f"(d[3])
        : "r"(a[0]), "r"(a[1]), "r"(a[2]), "r"(a[3]), "r"(b0), "r"(b1));
}

__device__ __forceinline__ void cp_async16(uint32_t dst_smem, const void* src) {
    asm volatile("cp.async.cg.shared.global [%0], [%1], 16;"
                 :: "r"(dst_smem), "l"(src));
}

// ============================================================================
// Kernel 0: softmax mix + modulate + demodulate -> fp16 fragment-ordered g_wt.
// Fragment layout (halves): [b][tap][wo(2)][kt(4)][mt(2)][lane(32)][pos(8)]
//   for mma.m16n8k16 A (row-major 16x16):
//   o = wo*32+mt*16+row, c = kt*16+kk; rA = (kk>=8)*2 + (row>=8);
//   lane = (row&7)*4 + ((kk&7)>>1); pos = rA*2 + (kk&1)
// ============================================================================
__global__ void weight_kernel(const float* __restrict__ mod,
                              const float* __restrict__ kmod,
                              const float* __restrict__ cw) {
    int o = blockIdx.x;
    int b = blockIdx.y;
    int i = threadIdx.x;  // input channel 0..63

    float k0 = kmod[b * NK + 0], k1 = kmod[b * NK + 1];
    float k2 = kmod[b * NK + 2], k3 = kmod[b * NK + 3];
    float m = fmaxf(fmaxf(k0, k1), fmaxf(k2, k3));
    float e0 = __expf(k0 - m), e1 = __expf(k1 - m);
    float e2 = __expf(k2 - m), e3 = __expf(k3 - m);
    float inv = 1.0f / (e0 + e1 + e2 + e3);
    float a0 = e0 * inv, a1 = e1 * inv, a2 = e2 * inv, a3 = e3 * inv;

    float mi = mod[b * C + i] + 1.0f;

    float wv[9];
    float ss = 0.0f;
#pragma unroll
    for (int k = 0; k < 9; k++) {
        int base = (o * C + i) * 9 + k;
        const int stride = O * C * 9;
        float v = a0 * cw[base] + a1 * cw[stride + base] +
                  a2 * cw[2 * stride + base] + a3 * cw[3 * stride + base];
        v *= mi;
        wv[k] = v;
        ss += v * v;
    }
#pragma unroll
    for (int off = 16; off; off >>= 1)
        ss += __shfl_xor_sync(0xffffffffu, ss, off);
    __shared__ float sh[2];
    if ((i & 31) == 0) sh[i >> 5] = ss;
    __syncthreads();
    float tot = sh[0] + sh[1];
    float innorm = rsqrtf(fmaxf(tot, 1e-8f));

    // fragment coordinates for (o, c=i)
    int wo = o >> 5;
    int m5 = o & 31;
    int mt = m5 >> 4;
    int row = m5 & 15;
    int kt = i >> 4;
    int kk = i & 15;
    int rA = ((kk >= 8) ? 2 : 0) + ((row >= 8) ? 1 : 0);
    int lane = ((row & 7) << 2) | ((kk & 7) >> 1);
    int pos = rA * 2 + (kk & 1);

#pragma unroll
    for (int k = 0; k < 9; k++) {
        long long idx = (((((long long)(b * 9 + k) * 2 + wo) * 4 + kt) * 2 + mt)
                         * 32 + lane) * 8 + pos;
        g_wt[idx] = __float2half_rn(wv[k] * innorm);
    }

    if (o == 0 && i < GROUPS) {
        g_sum[b * GROUPS + i] = 0.0f;
        g_sumsq[b * GROUPS + i] = 0.0f;
    }
}

// ============================================================================
// Kernel 1: fp16 tensor-core conv (9 shifted GEMMs, m16n8k16) + GN stats.
// grid (16,16,B), 256 threads = 8 warps, 2 CTAs/SM.
// smem: xs2 [32 half2-planes][XSP2] channel-pair-packed halo tile (41984 B)
//       + 2 x fragment-ordered A tap buffers (16384 B)
// ============================================================================
__global__ void __launch_bounds__(256, 2)
conv_kernel(const float* __restrict__ x, float* __restrict__ y) {
    extern __shared__ char smem[];
    __half2* xs2 = (__half2*)smem;                                // 32*XSP2
    __half* as_h = (__half*)(smem + NPLANE2 * XSP2 * 4);          // 2*A_TAP_HALVES
    __shared__ float gsum[GROUPS], gsq[GROUPS];

    int b = blockIdx.z;
    int h0 = blockIdx.y * 16;
    int w0 = blockIdx.x * 16;
    int tid = threadIdx.x;
    int wid = tid >> 5, lane = tid & 31;
    int wo = wid & 1;        // O half
    int wn = wid >> 1;       // pixel quarter: tile rows 4*wn..4*wn+3
    int g2 = lane >> 2;      // 0..7
    int qp = lane & 3;       // 0..3

    if (tid < GROUPS) { gsum[tid] = 0.0f; gsq[tid] = 0.0f; }

    const __half* wtb = g_wt + (long long)b * 9 * O * C;
    uint32_t as_smem = (uint32_t)__cvta_generic_to_shared(as_h);

    // prologue: A tap0 -> buf0 (8192 B = 512 x 16B, 2 chunks/thread)
#pragma unroll
    for (int j = 0; j < 2; j++) {
        int chunk = tid + j * 256;
        cp_async16(as_smem + chunk * 16, wtb + chunk * 8);
    }
    asm volatile("cp.async.commit_group;");

    // ---- stage x halo tile as channel-pair half2 (zero padded) ----
    const float* xb = x + (long long)b * C * HH * WW;
    for (int idx = tid; idx < NPLANE2 * 324; idx += 256) {
        int ci2 = idx / 324;
        int rem = idx - ci2 * 324;
        int rr = rem / 18;
        int cc = rem - rr * 18;
        int gh = h0 + rr - 1;
        int gw = w0 + cc - 1;
        float v0 = 0.0f, v1 = 0.0f;
        if ((unsigned)gh < HH && (unsigned)gw < WW) {
            const float* p = xb + (2 * ci2) * (HH * WW) + gh * WW + gw;
            v0 = p[0];
            v1 = p[HH * WW];
        }
        xs2[ci2 * XSP2 + rr * 18 + cc] = __floats2half2_rn(v0, v1);
    }
    asm volatile("cp.async.wait_group 0;");
    __syncthreads();

    float acc[2][8][4];
#pragma unroll
    for (int mt = 0; mt < 2; mt++)
#pragma unroll
        for (int nt = 0; nt < 8; nt++)
#pragma unroll
            for (int r = 0; r < 4; r++) acc[mt][nt][r] = 0.0f;

#pragma unroll 1
    for (int tap = 0; tap < 9; tap++) {
        int buf = tap & 1;
        if (tap < 8) {
            const __half* src = wtb + (tap + 1) * (O * C);
            uint32_t dst = as_smem + (buf ^ 1) * A_TAP_BYTES;
#pragma unroll
            for (int j = 0; j < 2; j++) {
                int chunk = tid + j * 256;
                cp_async16(dst + chunk * 16, src + chunk * 8);
            }
            asm volatile("cp.async.commit_group;");
        }

        int kh = tap / 3;
        int kw = tap - kh * 3;
        // A fragments: base for this warp's wo
        const uint4* a_base = (const uint4*)(as_h + buf * A_TAP_HALVES) +
                              (wo * 4) * 2 * 32 + lane;   // + (kt*2+mt)*32
        const __half2* b_base = xs2 + qp * XSP2 + (wn * 4 + kh) * 18 + kw + g2;

#pragma unroll
        for (int kt = 0; kt < 4; kt++) {
            uint4 af0 = a_base[(kt * 2 + 0) * 32];
            uint4 af1 = a_base[(kt * 2 + 1) * 32];
            const __half2* bp = b_base + kt * 8 * XSP2;
#pragma unroll
            for (int nt = 0; nt < 8; nt++) {
                int po = (nt >> 1) * 18 + (nt & 1) * 8;
                uint32_t b0 = *(const uint32_t*)(bp + po);
                uint32_t b1 = *(const uint32_t*)(bp + 4 * XSP2 + po);
                mma_f16(acc[0][nt], (const uint32_t*)&af0, b0, b1);
                mma_f16(acc[1][nt], (const uint32_t*)&af1, b0, b1);
            }
        }

        if (tap < 8) asm volatile("cp.async.wait_group 0;");
        __syncthreads();
    }

    // ---- store conv output (fp32) + GN partial stats ----
    float* yb = y + (long long)b * O * HH * WW;
    float s[2][2] = {{0, 0}, {0, 0}}, s2[2][2] = {{0, 0}, {0, 0}};
#pragma unroll
    for (int mt = 0; mt < 2; mt++) {
#pragma unroll
        for (int nt = 0; nt < 8; nt++) {
            int gh = h0 + wn * 4 + (nt >> 1);
            int gw = w0 + (nt & 1) * 8 + 2 * qp;
            int o_lo = wo * 32 + mt * 16 + g2;
            float c0 = acc[mt][nt][0], c1 = acc[mt][nt][1];
            float c2 = acc[mt][nt][2], c3 = acc[mt][nt][3];
            *(float2*)(yb + o_lo * (HH * WW) + gh * WW + gw) = make_float2(c0, c1);
            *(float2*)(yb + (o_lo + 8) * (HH * WW) + gh * WW + gw) = make_float2(c2, c3);
            s[mt][0] += c0 + c1;  s2[mt][0] += c0 * c0 + c1 * c1;
            s[mt][1] += c2 + c3;  s2[mt][1] += c2 * c2 + c3 * c3;
        }
    }
#pragma unroll
    for (int off = 16; off; off >>= 1) {
#pragma unroll
        for (int mt = 0; mt < 2; mt++)
#pragma unroll
            for (int hi = 0; hi < 2; hi++) {
                s[mt][hi]  += __shfl_xor_sync(0xffffffffu, s[mt][hi], off);
                s2[mt][hi] += __shfl_xor_sync(0xffffffffu, s2[mt][hi], off);
            }
    }
    if (lane == 0) {
#pragma unroll
        for (int mt = 0; mt < 2; mt++)
#pragma unroll
            for (int hi = 0; hi < 2; hi++) {
                int g = wo * 4 + mt * 2 + hi;
                atomicAdd(&gsum[g], s[mt][hi]);
                atomicAdd(&gsq[g], s2[mt][hi]);
            }
    }
    __syncthreads();
    if (tid < GROUPS) {
        atomicAdd(&g_sum[b * GROUPS + tid], gsum[tid]);
        atomicAdd(&g_sumsq[b * GROUPS + tid], gsq[tid]);
    }
}

// ============================================================================
// Kernel 2: GroupNorm finalize + SiLU, in-place, float4 vectorized.
// ============================================================================
__global__ void norm_kernel(float* __restrict__ y,
                            const float* __restrict__ gamma,
                            const float* __restrict__ beta) {
    long long i = (long long)blockIdx.x * blockDim.x + threadIdx.x;
    long long base = i * 4;
    int cidx = (int)(base >> 16);
    int b = cidx >> 6;
    int c = cidx & 63;
    int g = c >> 3;

    const float invN = 1.0f / (8.0f * HH * WW);
    float mean = g_sum[b * GROUPS + g] * invN;
    float var = g_sumsq[b * GROUPS + g] * invN - mean * mean;
    float istd = rsqrtf(var + 1e-5f);
    float ga = gamma[c], be = beta[c];

    float4 v = *(float4*)&y[base];
    float* vp = &v.x;
#pragma unroll
    for (int k = 0; k < 4; k++) {
        float t = (vp[k] - mean) * istd * ga + be;
        vp[k] = t / (1.0f + __expf(-t));
    }
    *(float4*)&y[base] = v;
}

// ============================================================================
extern "C" void kernel_launch(void* const* d_in, const int* in_sizes, int n_in,
                              void* d_out, int out_size) {
    const float* x     = (const float*)d_in[0];
    const float* mod   = (const float*)d_in[1];
    const float* kmod  = (const float*)d_in[2];
    const float* cw    = (const float*)d_in[3];
    const float* gamma = (const float*)d_in[4];
    const float* beta  = (const float*)d_in[5];
    float* out = (float*)d_out;

    const int smem = NPLANE2 * XSP2 * 4 + 2 * A_TAP_BYTES;  // 41984+16384 = 58368
    cudaFuncSetAttribute(conv_kernel,
                         cudaFuncAttributeMaxDynamicSharedMemorySize, smem);

    weight_kernel<<<dim3(O, B), 64>>>(mod, kmod, cw);
    conv_kernel<<<dim3(16, 16, B), 256, smem>>>(x, out);
    norm_kernel<<<(B * O * HH * WW / 4) / 256, 256>>>(out, gamma, beta);
}